// round 17
// baseline (speedup 1.0000x reference)
#include <cuda_runtime.h>
#include <cuda_fp16.h>
#include <cstdint>
#include <math.h>

// ---------------------------------------------------------------------------
// Problem constants
// ---------------------------------------------------------------------------
#define BATCH   8
#define DIMC    512
#define SPATIAL 1024
#define NTOK    (BATCH*SPATIAL)  // 8192
#define HEADS   8
#define HDIM    64
#define KVLEN   77
#define KVDIM   1024

// ---------------------------------------------------------------------------
// Scratch buffers
// ---------------------------------------------------------------------------
__device__ float  g_x  [(size_t)NTOK * DIMC];           // fp32 residual stream
__device__ float  g_bFfp[4096];                         // interleaved ffp bias
__device__ float  g_gnstats[BATCH * 32 * 2];            // groupnorm mu/inv
__device__ __half g_th  [(size_t)NTOK * DIMC];
__device__ __half g_qkvh[(size_t)NTOK * 1536];
__device__ __half g_qh  [(size_t)NTOK * DIMC];
__device__ __half g_kvh [(size_t)(BATCH*KVLEN) * 1024];
__device__ __half g_kv2h[(size_t)(BATCH*KVLEN) * 1024];
__device__ __half g_glh [(size_t)NTOK * 2048];
__device__ __half g_xh  [(size_t)NTOK * DIMC];
// half transposed weights [N, K]
__device__ __half g_whFcIn[(size_t)512 * 512];
__device__ __half g_whQkv [(size_t)1536 * 512];
__device__ __half g_whA1o [(size_t)512 * 512];
__device__ __half g_whA2q [(size_t)512 * 512];
__device__ __half g_whA2o [(size_t)512 * 512];
__device__ __half g_whKv2 [(size_t)1024 * 1024];
__device__ __half g_whFfp [(size_t)4096 * 512];         // a/gate interleaved rows
__device__ __half g_whFfo [(size_t)512 * 2048];
__device__ __half g_whFco [(size_t)512 * 512];

// ---------------------------------------------------------------------------
// Helpers
// ---------------------------------------------------------------------------
__device__ __forceinline__ float warpSum(float v) {
    #pragma unroll
    for (int o = 16; o > 0; o >>= 1) v += __shfl_xor_sync(0xffffffffu, v, o);
    return v;
}
__device__ __forceinline__ void mma_f16(float* d, const uint32_t* a, const uint32_t* b) {
    asm volatile(
        "mma.sync.aligned.m16n8k16.row.col.f32.f16.f16.f32 "
        "{%0,%1,%2,%3}, {%4,%5,%6,%7}, {%8,%9}, {%0,%1,%2,%3};"
        : "+f"(d[0]), "+f"(d[1]), "+f"(d[2]), "+f"(d[3])
        : "r"(a[0]), "r"(a[1]), "r"(a[2]), "r"(a[3]), "r"(b[0]), "r"(b[1]));
}
__device__ __forceinline__ void ldsm4(uint32_t& r0, uint32_t& r1,
                                      uint32_t& r2, uint32_t& r3, uint32_t addr) {
    asm volatile("ldmatrix.sync.aligned.m8n8.x4.shared.b16 {%0,%1,%2,%3}, [%4];"
                 : "=r"(r0), "=r"(r1), "=r"(r2), "=r"(r3) : "r"(addr));
}
__device__ __forceinline__ void ldsm4t(uint32_t& r0, uint32_t& r1,
                                       uint32_t& r2, uint32_t& r3, uint32_t addr) {
    asm volatile("ldmatrix.sync.aligned.m8n8.x4.trans.shared.b16 {%0,%1,%2,%3}, [%4];"
                 : "=r"(r0), "=r"(r1), "=r"(r2), "=r"(r3) : "r"(addr));
}
__device__ __forceinline__ void cp_async16(uint32_t dst, const void* src, int bytes) {
    asm volatile("cp.async.cg.shared.global [%0], [%1], 16, %2;\n"
                 :: "r"(dst), "l"(src), "r"(bytes));
}
__device__ __forceinline__ void cp_commit() { asm volatile("cp.async.commit_group;\n"); }
__device__ __forceinline__ void cp_wait1()  { asm volatile("cp.async.wait_group 1;\n"); }
__device__ __forceinline__ void cp_wait0()  { asm volatile("cp.async.wait_group 0;\n"); }
__device__ __forceinline__ float gelu_f(float v) {
    return 0.5f * v * (1.f + erff(v * 0.70710678118654752f));
}

// ---------------------------------------------------------------------------
// GroupNorm stats: one block per (batch, group). Coalesced read only.
// ---------------------------------------------------------------------------
__global__ void gn_stats_kernel(const float* __restrict__ qin,
                                float* __restrict__ stats) {
    const int blk = blockIdx.x;
    const float* base = qin + (size_t)blk * 16 * SPATIAL;

    float s = 0.f, s2 = 0.f;
    for (int i = threadIdx.x; i < 16 * SPATIAL; i += 256) {
        float v = base[i];
        s += v; s2 += v * v;
    }
    __shared__ float red[2][8];
    s = warpSum(s); s2 = warpSum(s2);
    int wid = threadIdx.x >> 5, lid = threadIdx.x & 31;
    if (lid == 0) { red[0][wid] = s; red[1][wid] = s2; }
    __syncthreads();
    if (threadIdx.x == 0) {
        float a = 0.f, c = 0.f;
        #pragma unroll
        for (int i = 0; i < 8; i++) { a += red[0][i]; c += red[1][i]; }
        const float mu  = a * (1.f / 16384.f);
        const float var = c * (1.f / 16384.f) - mu * mu;
        stats[blk * 2]     = mu;
        stats[blk * 2 + 1] = rsqrtf(var + 1e-6f);
    }
}

// ---------------------------------------------------------------------------
// GroupNorm normalize + transpose to token-major (32x32 tiles, coalesced).
// ---------------------------------------------------------------------------
__global__ void gn_write_kernel(const float* __restrict__ qin,
                                const float* __restrict__ stats,
                                const float* __restrict__ gamma,
                                const float* __restrict__ beta,
                                __half* __restrict__ out) {
    __shared__ float tile[32][33];
    const int b  = blockIdx.z;
    const int c0 = blockIdx.y * 32;
    const int s0 = blockIdx.x * 32;
    const int x = threadIdx.x, y = threadIdx.y;

    #pragma unroll
    for (int i = 0; i < 32; i += 8)
        tile[y + i][x] = qin[((size_t)(b * DIMC + c0 + y + i)) * SPATIAL + s0 + x];
    __syncthreads();

    const int c = c0 + x;
    const int sb = (b * 32 + (c >> 4)) * 2;
    const float mu  = stats[sb];
    const float inv = stats[sb + 1];
    const float gm = gamma[c], bt = beta[c];
    #pragma unroll
    for (int i = 0; i < 32; i += 8) {
        float v = (tile[x][y + i] - mu) * inv * gm + bt;
        out[((size_t)(b * SPATIAL + s0 + y + i)) * DIMC + c] = __float2half(v);
    }
}

// ---------------------------------------------------------------------------
// LayerNorm (fp32 in, half out). One warp per 512-dim row.
// ---------------------------------------------------------------------------
__global__ void layernorm_kernel(const float* __restrict__ x,
                                 const float* __restrict__ gamma,
                                 const float* __restrict__ beta,
                                 __half* __restrict__ out, int rows) {
    int row = blockIdx.x * 8 + (threadIdx.x >> 5);
    if (row >= rows) return;
    int lid = threadIdx.x & 31;
    const float4* xr = (const float4*)(x + (size_t)row * DIMC);

    float4 vals[4];
    float s = 0.f, s2 = 0.f;
    #pragma unroll
    for (int i = 0; i < 4; i++) {
        float4 v = xr[lid + 32 * i];
        vals[i] = v;
        s  += v.x + v.y + v.z + v.w;
        s2 += v.x*v.x + v.y*v.y + v.z*v.z + v.w*v.w;
    }
    s = warpSum(s); s2 = warpSum(s2);
    const float mu  = s * (1.f / 512.f);
    const float inv = rsqrtf(s2 * (1.f / 512.f) - mu * mu + 1e-5f);

    __half2* orow = (__half2*)(out + (size_t)row * DIMC);
    const float4* g4 = (const float4*)gamma;
    const float4* b4 = (const float4*)beta;
    #pragma unroll
    for (int i = 0; i < 4; i++) {
        int idx = lid + 32 * i;
        float4 v = vals[i], g = g4[idx], b = b4[idx];
        float ox = (v.x - mu) * inv * g.x + b.x;
        float oy = (v.y - mu) * inv * g.y + b.y;
        float oz = (v.z - mu) * inv * g.z + b.z;
        float ow = (v.w - mu) * inv * g.w + b.w;
        orow[idx * 2]     = __floats2half2_rn(ox, oy);
        orow[idx * 2 + 1] = __floats2half2_rn(oz, ow);
    }
}

// ---------------------------------------------------------------------------
// Batched transpose + f32->f16 (12 weights, ONE launch).
// ---------------------------------------------------------------------------
#define NJOBS 12
struct TrJobs {
    const float* src[NJOBS];
    __half*      dst[NJOBS];
    int R[NJOBS], C[NJOBS], ileave[NJOBS];
    int tstart[NJOBS + 1];
};

__global__ void trcvt_all_kernel(TrJobs jobs) {
    __shared__ float tile[32][33];
    const int flat = blockIdx.x;
    int j = 0;
    #pragma unroll
    for (int i = 0; i < NJOBS; i++)
        if (flat >= jobs.tstart[i + 1]) j = i + 1;
    const int lt = flat - jobs.tstart[j];
    const int C = jobs.C[j], R = jobs.R[j];
    const int ctiles = C >> 5;
    const int c0 = (lt % ctiles) * 32;
    const int r0 = (lt / ctiles) * 32;
    const float* src = jobs.src[j];
    __half* dst = jobs.dst[j];
    const int il = jobs.ileave[j];
    const int halfC = C >> 1;

    int x = threadIdx.x, y = threadIdx.y;
    #pragma unroll
    for (int i = 0; i < 32; i += 8)
        tile[y + i][x] = src[(size_t)(r0 + y + i) * C + c0 + x];
    __syncthreads();
    #pragma unroll
    for (int i = 0; i < 32; i += 8) {
        int d = c0 + y + i;
        if (il) d = (d < halfC) ? 2 * d : 2 * (d - halfC) + 1;
        dst[(size_t)d * R + r0 + x] = __float2half(tile[x][y + i]);
    }
}

// f32 -> f16 linear convert
__global__ void cvt_kernel(const float* __restrict__ src,
                           __half* __restrict__ dst, int n) {
    int i = blockIdx.x * 256 + threadIdx.x;
    if (i < n) dst[i] = __float2half(src[i]);
}

// interleave ffp bias
__global__ void bias_ileave_kernel(const float* __restrict__ b,
                                   float* __restrict__ dst) {
    int j = blockIdx.x * 256 + threadIdx.x;
    if (j < 2048) {
        dst[2 * j]     = b[j];
        dst[2 * j + 1] = b[2048 + j];
    }
}

// ===========================================================================
// Fused flash self-attention (R16 pipelined version, unchanged).
// ===========================================================================
#define SCL 0.125f
#define FH 72
#define PH 136
#define FS_SQ   0
#define FS_SK0  (128*FH)
#define FS_SK1  (2*128*FH)
#define FS_SV   (3*128*FH)
#define FS_SP   (4*128*FH)
#define FS_TOTAL_H (FS_SP + 128*PH)   // 54272 halves = 108544 B

__global__ void __launch_bounds__(256) flash_self_kernel(
    const __half* __restrict__ qkv, __half* __restrict__ outp) {
    extern __shared__ __half smh[];
    __half* sP = smh + FS_SP;

    const int b  = blockIdx.y >> 3;
    const int h  = blockIdx.y & 7;
    const int q0 = blockIdx.x * 128;
    const int tid = threadIdx.x;
    const int warp = tid >> 5;
    const int lane = tid & 31;
    const int g  = lane >> 2;
    const int tg = lane & 3;
    const int wm = warp * 16;

    const uint32_t smb = (uint32_t)__cvta_generic_to_shared(smh);
    const uint32_t lr = lane & 15;
    const uint32_t lh = (lane >> 4) * 8;

    const int lrow = tid >> 3;
    const int lc8  = (tid & 7) * 8;

    #pragma unroll
    for (int r = 0; r < 4; r++) {
        int row = lrow + r * 32;
        cp_async16(smb + (uint32_t)(FS_SQ + row * FH + lc8) * 2,
                   qkv + (size_t)(b * 1024 + q0 + row) * 1536 + h * 64 + lc8, 16);
    }
    cp_commit();
    {
        const __half* kb = qkv + (size_t)(b * 1024) * 1536 + h * 64 + 512;
        #pragma unroll
        for (int r = 0; r < 4; r++) {
            int row = lrow + r * 32;
            cp_async16(smb + (uint32_t)(FS_SK0 + row * FH + lc8) * 2,
                       kb + (size_t)row * 1536 + lc8, 16);
        }
    }
    cp_commit();
    cp_wait1();
    __syncthreads();

    uint32_t qf[4][4];
    {
        const uint32_t qbase = smb + (uint32_t)(FS_SQ + (wm + lr) * FH + lh) * 2;
        #pragma unroll
        for (int kc = 0; kc < 4; kc++)
            ldsm4(qf[kc][0], qf[kc][1], qf[kc][2], qf[kc][3], qbase + kc * 32);
    }

    float m_[2] = {-1e30f, -1e30f};
    float l_[2] = {0.f, 0.f};
    float acco[8][4];
    #pragma unroll
    for (int i = 0; i < 8; i++)
        #pragma unroll
        for (int r = 0; r < 4; r++) acco[i][r] = 0.f;

    const uint32_t pbase = smb + (uint32_t)(FS_SP + (wm + lr) * PH + lh) * 2;
    const uint32_t vbase = smb + (uint32_t)(FS_SV + lr * FH + lh) * 2;

    for (int j = 0; j < 8; j++) {
        cp_wait0();
        __syncthreads();

        {
            const __half* vb = qkv + (size_t)(b * 1024 + j * 128) * 1536 + h * 64 + 1024;
            #pragma unroll
            for (int r = 0; r < 4; r++) {
                int row = lrow + r * 32;
                cp_async16(smb + (uint32_t)(FS_SV + row * FH + lc8) * 2,
                           vb + (size_t)row * 1536 + lc8, 16);
            }
        }
        cp_commit();
        if (j + 1 < 8) {
            const int kbuf = ((j + 1) & 1) ? FS_SK1 : FS_SK0;
            const __half* kb = qkv + (size_t)(b * 1024 + (j + 1) * 128) * 1536 + h * 64 + 512;
            #pragma unroll
            for (int r = 0; r < 4; r++) {
                int row = lrow + r * 32;
                cp_async16(smb + (uint32_t)(kbuf + row * FH + lc8) * 2,
                           kb + (size_t)row * 1536 + lc8, 16);
            }
            cp_commit();
        }

        const uint32_t kbase = smb +
            (uint32_t)(((j & 1) ? FS_SK1 : FS_SK0) + lr * FH + lh) * 2;
        float accs[16][4];
        #pragma unroll
        for (int nt = 0; nt < 16; nt++)
            #pragma unroll
            for (int r = 0; r < 4; r++) accs[nt][r] = 0.f;

        #pragma unroll
        for (int kc = 0; kc < 4; kc++) {
            const uint32_t ka = kbase + kc * 32;
            #pragma unroll
            for (int p = 0; p < 8; p++) {
                uint32_t b0, b1, b2, b3;
                ldsm4(b0, b1, b2, b3, ka + (uint32_t)(p * 16 * FH) * 2);
                uint32_t bf0[2] = {b0, b2};
                uint32_t bf1[2] = {b1, b3};
                mma_f16(accs[2 * p],     qf[kc], bf0);
                mma_f16(accs[2 * p + 1], qf[kc], bf1);
            }
        }

        float mx0 = -1e30f, mx1 = -1e30f;
        #pragma unroll
        for (int nt = 0; nt < 16; nt++) {
            mx0 = fmaxf(mx0, fmaxf(accs[nt][0], accs[nt][1]));
            mx1 = fmaxf(mx1, fmaxf(accs[nt][2], accs[nt][3]));
        }
        mx0 = fmaxf(mx0, __shfl_xor_sync(0xffffffffu, mx0, 1));
        mx0 = fmaxf(mx0, __shfl_xor_sync(0xffffffffu, mx0, 2));
        mx1 = fmaxf(mx1, __shfl_xor_sync(0xffffffffu, mx1, 1));
        mx1 = fmaxf(mx1, __shfl_xor_sync(0xffffffffu, mx1, 2));
        const float mn0 = fmaxf(m_[0], mx0);
        const float mn1 = fmaxf(m_[1], mx1);
        const float c0 = __expf((m_[0] - mn0) * SCL);
        const float c1 = __expf((m_[1] - mn1) * SCL);
        l_[0] *= c0; l_[1] *= c1;
        #pragma unroll
        for (int nt = 0; nt < 8; nt++) {
            acco[nt][0] *= c0; acco[nt][1] *= c0;
            acco[nt][2] *= c1; acco[nt][3] *= c1;
        }
        float rs0 = 0.f, rs1 = 0.f;
        __half* p0 = sP + (wm + g) * PH + 2 * tg;
        __half* p1 = sP + (wm + g + 8) * PH + 2 * tg;
        #pragma unroll
        for (int nt = 0; nt < 16; nt++) {
            const float e0 = __expf((accs[nt][0] - mn0) * SCL);
            const float e1 = __expf((accs[nt][1] - mn0) * SCL);
            const float e2 = __expf((accs[nt][2] - mn1) * SCL);
            const float e3 = __expf((accs[nt][3] - mn1) * SCL);
            rs0 += e0 + e1; rs1 += e2 + e3;
            *(__half2*)(p0 + nt * 8) = __floats2half2_rn(e0, e1);
            *(__half2*)(p1 + nt * 8) = __floats2half2_rn(e2, e3);
        }
        rs0 += __shfl_xor_sync(0xffffffffu, rs0, 1);
        rs0 += __shfl_xor_sync(0xffffffffu, rs0, 2);
        rs1 += __shfl_xor_sync(0xffffffffu, rs1, 1);
        rs1 += __shfl_xor_sync(0xffffffffu, rs1, 2);
        l_[0] += rs0; l_[1] += rs1;
        m_[0] = mn0; m_[1] = mn1;

        if (j + 1 < 8) cp_wait1(); else cp_wait0();
        __syncthreads();

        #pragma unroll
        for (int kc = 0; kc < 8; kc++) {
            uint32_t af[4];
            ldsm4(af[0], af[1], af[2], af[3], pbase + kc * 32);
            const uint32_t va = vbase + (uint32_t)(kc * 16 * FH) * 2;
            #pragma unroll
            for (int p = 0; p < 4; p++) {
                uint32_t t0, t1, t2, t3;
                ldsm4t(t0, t1, t2, t3, va + (uint32_t)(p * 16) * 2);
                uint32_t bf0[2] = {t0, t1};
                uint32_t bf1[2] = {t2, t3};
                mma_f16(acco[2 * p],     af, bf0);
                mma_f16(acco[2 * p + 1], af, bf1);
            }
        }
    }

    const float i0 = 1.f / l_[0];
    const float i1 = 1.f / l_[1];
    const int row0 = b * 1024 + q0 + wm + g;
    #pragma unroll
    for (int nt = 0; nt < 8; nt++) {
        const int col = h * 64 + nt * 8 + 2 * tg;
        *(__half2*)(outp + (size_t)row0 * 512 + col) =
            __floats2half2_rn(acco[nt][0] * i0, acco[nt][1] * i0);
        *(__half2*)(outp + (size_t)(row0 + 8) * 512 + col) =
            __floats2half2_rn(acco[nt][2] * i1, acco[nt][3] * i1);
    }
}

// ===========================================================================
// Fused flash cross-attention (kv 77 -> padded 80), fp16, trans-V.
// ===========================================================================
#define CH 88
#define CF_SQ   0
#define CF_SK   (128*FH)
#define CF_SV   (CF_SK + 80*FH)
#define CF_SP   (CF_SV + 80*FH)
#define CF_TOTAL_H (CF_SP + 128*CH)

__global__ void __launch_bounds__(256) flash_cross_kernel(
    const __half* __restrict__ qsrc, const __half* __restrict__ kv2,
    __half* __restrict__ outp) {
    extern __shared__ __half smh[];
    __half* sP = smh + CF_SP;

    const int b  = blockIdx.y >> 3;
    const int h  = blockIdx.y & 7;
    const int q0 = blockIdx.x * 128;
    const int tid = threadIdx.x;
    const int warp = tid >> 5;
    const int lane = tid & 31;
    const int g  = lane >> 2;
    const int tg = lane & 3;
    const int wm = warp * 16;

    const uint32_t smb = (uint32_t)__cvta_generic_to_shared(smh);
    const uint32_t lr = lane & 15;
    const uint32_t lh = (lane >> 4) * 8;

    for (int i = tid; i < 1024; i += 256) {
        int row = i >> 3;
        int c8  = (i & 7) * 8;
        cp_async16(smb + (uint32_t)(CF_SQ + row * FH + c8) * 2,
                   qsrc + (size_t)(b * 1024 + q0 + row) * 512 + h * 64 + c8, 16);
    }
    for (int i = tid; i < 640; i += 256) {
        int row = i >> 3;
        int c8  = (i & 7) * 8;
        int bytes = (row < KVLEN) ? 16 : 0;
        const __half* base = kv2 + (size_t)(b * KVLEN + row) * 1024 + h * 64;
        cp_async16(smb + (uint32_t)(CF_SK + row * FH + c8) * 2, base + c8, bytes);
        cp_async16(smb + (uint32_t)(CF_SV + row * FH + c8) * 2, base + 512 + c8, bytes);
    }
    cp_commit(); cp_wait0();
    __syncthreads();

    uint32_t qf[4][4];
    {
        const uint32_t qbase = smb + (uint32_t)(CF_SQ + (wm + lr) * FH + lh) * 2;
        #pragma unroll
        for (int kc = 0; kc < 4; kc++)
            ldsm4(qf[kc][0], qf[kc][1], qf[kc][2], qf[kc][3], qbase + kc * 32);
    }

    float accs[10][4];
    #pragma unroll
    for (int nt = 0; nt < 10; nt++)
        #pragma unroll
        for (int r = 0; r < 4; r++) accs[nt][r] = 0.f;
    {
        const uint32_t kbase = smb + (uint32_t)(CF_SK + lr * FH + lh) * 2;
        #pragma unroll
        for (int kc = 0; kc < 4; kc++) {
            const uint32_t ka = kbase + kc * 32;
            #pragma unroll
            for (int p = 0; p < 5; p++) {
                uint32_t b0, b1, b2, b3;
                ldsm4(b0, b1, b2, b3, ka + (uint32_t)(p * 16 * FH) * 2);
                uint32_t bf0[2] = {b0, b2};
                uint32_t bf1[2] = {b1, b3};
                mma_f16(accs[2 * p],     qf[kc], bf0);
                mma_f16(accs[2 * p + 1], qf[kc], bf1);
            }
        }
    }

    #pragma unroll
    for (int nt = 0; nt < 10; nt++) {
        const int col0 = nt * 8 + 2 * tg;
        if (col0 >= KVLEN)     { accs[nt][0] = -1e30f; accs[nt][2] = -1e30f; }
        if (col0 + 1 >= KVLEN) { accs[nt][1] = -1e30f; accs[nt][3] = -1e30f; }
    }
    float mx0 = -1e30f, mx1 = -1e30f;
    #pragma unroll
    for (int nt = 0; nt < 10; nt++) {
        mx0 = fmaxf(mx0, fmaxf(accs[nt][0], accs[nt][1]));
        mx1 = fmaxf(mx1, fmaxf(accs[nt][2], accs[nt][3]));
    }
    mx0 = fmaxf(mx0, __shfl_xor_sync(0xffffffffu, mx0, 1));
    mx0 = fmaxf(mx0, __shfl_xor_sync(0xffffffffu, mx0, 2));
    mx1 = fmaxf(mx1, __shfl_xor_sync(0xffffffffu, mx1, 1));
    mx1 = fmaxf(mx1, __shfl_xor_sync(0xffffffffu, mx1, 2));

    float rs0 = 0.f, rs1 = 0.f;
    __half* p0 = sP + (wm + g) * CH + 2 * tg;
    __half* p1 = sP + (wm + g + 8) * CH + 2 * tg;
    #pragma unroll
    for (int nt = 0; nt < 10; nt++) {
        const float e0 = __expf((accs[nt][0] - mx0) * SCL);
        const float e1 = __expf((accs[nt][1] - mx0) * SCL);
        const float e2 = __expf((accs[nt][2] - mx1) * SCL);
        const float e3 = __expf((accs[nt][3] - mx1) * SCL);
        rs0 += e0 + e1; rs1 += e2 + e3;
        *(__half2*)(p0 + nt * 8) = __floats2half2_rn(e0, e1);
        *(__half2*)(p1 + nt * 8) = __floats2half2_rn(e2, e3);
    }
    rs0 += __shfl_xor_sync(0xffffffffu, rs0, 1);
    rs0 += __shfl_xor_sync(0xffffffffu, rs0, 2);
    rs1 += __shfl_xor_sync(0xffffffffu, rs1, 1);
    rs1 += __shfl_xor_sync(0xffffffffu, rs1, 2);
    __syncwarp();

    float acco[8][4];
    #pragma unroll
    for (int nt = 0; nt < 8; nt++)
        #pragma unroll
        for (int r = 0; r < 4; r++) acco[nt][r] = 0.f;
    {
        const uint32_t pb = smb + (uint32_t)(CF_SP + (wm + lr) * CH + lh) * 2;
        const uint32_t vb = smb + (uint32_t)(CF_SV + lr * FH + lh) * 2;
        #pragma unroll
        for (int kc = 0; kc < 5; kc++) {
            uint32_t af[4];
            ldsm4(af[0], af[1], af[2], af[3], pb + kc * 32);
            const uint32_t va = vb + (uint32_t)(kc * 16 * FH) * 2;
            #pragma unroll
            for (int p = 0; p < 4; p++) {
                uint32_t t0, t1, t2, t3;
                ldsm4t(t0, t1, t2, t3, va + (uint32_t)(p * 16) * 2);
                uint32_t bf0[2] = {t0, t1};
                uint32_t bf1[2] = {t2, t3};
                mma_f16(acco[2 * p],     af, bf0);
                mma_f16(acco[2 * p + 1], af, bf1);
            }
        }
    }

    const float i0 = 1.f / rs0;
    const float i1 = 1.f / rs1;
    const int row0 = b * 1024 + q0 + wm + g;
    #pragma unroll
    for (int nt = 0; nt < 8; nt++) {
        const int col = h * 64 + nt * 8 + 2 * tg;
        *(__half2*)(outp + (size_t)row0 * 512 + col) =
            __floats2half2_rn(acco[nt][0] * i0, acco[nt][1] * i0);
        *(__half2*)(outp + (size_t)(row0 + 8) * 512 + col) =
            __floats2half2_rn(acco[nt][2] * i1, acco[nt][3] * i1);
    }
}

// ===========================================================================
// FP16 tensor-core GEMM, 64x64 warp tile: BM=128, BN=256, BK=32.
// 8 warps as 2m x 4n; per ks-step 4 A-LDSM + 4 B-LDSM -> 32 HMMA.
// 3-stage cp.async, 92KB smem (1 CTA/SM), single barrier per k-tile.
//   emode 0: plain (+Res fp32 add)
//   emode 3: GEGLU-paired interleaved a/gate -> Ch, ldc = N/2
//   emode 4: transposed-output write to [b,c,s] + qin residual.
// ===========================================================================
#define BM 128
#define BN 256
#define BK 32
#define GSTR 40
#define STG_BYTES ((BM + BN) * GSTR * 2)   // 30720
#define GEMM_SMEM (3 * STG_BYTES)          // 92160

__global__ void __launch_bounds__(256) gemm_f16_kernel(
    const __half* __restrict__ A, int lda,
    const __half* __restrict__ Bt, int ldb,
    float* __restrict__ Cf, __half* __restrict__ Ch, int ldc,
    const float* __restrict__ Res, int ldres,
    const float* __restrict__ bias,
    int M, int K, int emode) {

    extern __shared__ __half smh[];

    const int m0 = blockIdx.y * BM;
    const int n0 = blockIdx.x * BN;
    const int tid = threadIdx.x;
    const int warp = tid >> 5;
    const int lane = tid & 31;
    const int g  = lane >> 2;
    const int tg = lane & 3;
    const int wm = (warp >> 2) * 64;   // 2 m-groups
    const int wn = (warp & 3) * 64;    // 4 n-groups

    const uint32_t smem_u32 = (uint32_t)__cvta_generic_to_shared(smh);
    const int nk = K / BK;

    float acc[4][8][4];
    #pragma unroll
    for (int i = 0; i < 4; i++)
        #pragma unroll
        for (int j = 0; j < 8; j++)
            #pragma unroll
            for (int r = 0; r < 4; r++) acc[i][j][r] = 0.f;

    auto load_stage = [&](int stage, int k0) {
        const uint32_t abase = smem_u32 + (uint32_t)(stage * STG_BYTES);
        // A: 128 rows x 4 chunks = 512, 2 per thread
        #pragma unroll
        for (int i = 0; i < 2; i++) {
            int idx = tid + i * 256;
            int row = idx >> 2;
            int kc  = (idx & 3) * 8;
            int bytes = (m0 + row < M) ? 16 : 0;
            cp_async16(abase + (uint32_t)(row * GSTR + kc) * 2,
                       A + (long long)(m0 + row) * lda + k0 + kc, bytes);
        }
        // B: 256 rows x 4 chunks = 1024, 4 per thread
        const uint32_t bbase = abase + (uint32_t)(BM * GSTR * 2);
        #pragma unroll
        for (int i = 0; i < 4; i++) {
            int idx = tid + i * 256;
            int row = idx >> 2;
            int kc  = (idx & 3) * 8;
            cp_async16(bbase + (uint32_t)(row * GSTR + kc) * 2,
                       Bt + (long long)(n0 + row) * ldb + k0 + kc, 16);
        }
        cp_commit();
    };

    const uint32_t lm_off = (uint32_t)((lane & 15) * GSTR + ((lane >> 4) * 8)) * 2;
    const uint32_t a_lm = smem_u32 + (uint32_t)(wm * GSTR) * 2 + lm_off;
    const uint32_t b_lm = smem_u32 + (uint32_t)(BM * GSTR + wn * GSTR) * 2 + lm_off;

    auto compute_stage = [&](int stage) {
        const uint32_t so = (uint32_t)(stage * STG_BYTES);
        #pragma unroll
        for (int ks = 0; ks < 2; ks++) {
            const uint32_t kkb = ks * 32;
            uint32_t afr[4][4];
            #pragma unroll
            for (int mt = 0; mt < 4; mt++)
                ldsm4(afr[mt][0], afr[mt][1], afr[mt][2], afr[mt][3],
                      a_lm + so + (uint32_t)(mt * 16 * GSTR) * 2 + kkb);
            uint32_t bfr[8][2];
            #pragma unroll
            for (int p = 0; p < 4; p++) {
                uint32_t r0, r1, r2, r3;
                ldsm4(r0, r1, r2, r3, b_lm + so + (uint32_t)(p * 16 * GSTR) * 2 + kkb);
                bfr[2 * p][0]     = r0; bfr[2 * p][1]     = r2;
                bfr[2 * p + 1][0] = r1; bfr[2 * p + 1][1] = r3;
            }
            #pragma unroll
            for (int mt = 0; mt < 4; mt++)
                #pragma unroll
                for (int nt = 0; nt < 8; nt++)
                    mma_f16(acc[mt][nt], afr[mt], bfr[nt]);
        }
    };

    load_stage(0, 0);
    if (nk > 1) load_stage(1, BK);
    for (int kt = 0; kt < nk; kt++) {
        if (kt + 1 < nk) cp_wait1(); else cp_wait0();
        __syncthreads();
        if (kt + 2 < nk) load_stage((kt + 2) % 3, (kt + 2) * BK);
        compute_stage(kt % 3);
    }

    // ---- epilogue (vectorized) ----
    const int obatch = n0 >> 10;
    #pragma unroll
    for (int mt = 0; mt < 4; mt++) {
        #pragma unroll
        for (int nt = 0; nt < 8; nt++) {
            const int row0 = m0 + wm + mt * 16 + g;
            const int col0 = n0 + wn + nt * 8 + tg * 2;
            #pragma unroll
            for (int hh = 0; hh < 2; hh++) {
                const int row = row0 + hh * 8;
                if (row >= M) continue;
                float v0 = acc[mt][nt][2 * hh + 0];
                float v1 = acc[mt][nt][2 * hh + 1];
                if (emode == 4) {
                    v0 += bias[row]; v1 += bias[row];
                    const size_t o = ((size_t)(obatch * 512 + row)) * 1024 +
                                     (col0 & 1023);
                    float2 r = *(const float2*)(Res + o);
                    *(float2*)(Cf + o) = make_float2(v0 + r.x, v1 + r.y);
                    continue;
                }
                if (bias) { v0 += bias[col0]; v1 += bias[col0 + 1]; }
                if (emode == 3) {
                    Ch[(long long)row * ldc + (col0 >> 1)] =
                        __float2half(v0 * gelu_f(v1));
                    continue;
                }
                if (Res) {
                    float2 r = *(const float2*)(Res + (long long)row * ldres + col0);
                    v0 += r.x; v1 += r.y;
                }
                if (Cf) *(float2*)(Cf + (long long)row * ldc + col0) =
                            make_float2(v0, v1);
                if (Ch) *(__half2*)(Ch + (long long)row * ldc + col0) =
                            __floats2half2_rn(v0, v1);
            }
        }
    }
}

// ---------------------------------------------------------------------------
// Host side
// ---------------------------------------------------------------------------
static void gemm(const __half* A, int lda, const __half* Bt, int ldb,
                 float* Cf, __half* Ch, int ldc,
                 const float* Res, int ldres,
                 const float* bias, int M, int N, int K, int emode = 0) {
    dim3 grid(N / BN, (M + BM - 1) / BM);
    gemm_f16_kernel<<<grid, 256, GEMM_SMEM>>>(
        A, lda, Bt, ldb, Cf, Ch, ldc, Res, ldres, bias, M, K, emode);
}

extern "C" void kernel_launch(void* const* d_in, const int* in_sizes, int n_in,
                              void* d_out, int out_size) {
    const float* in_q     = (const float*)d_in[0];
    const float* in_kv    = (const float*)d_in[1];
    const float* gn_g     = (const float*)d_in[2];
    const float* gn_b     = (const float*)d_in[3];
    const float* ln2_g    = (const float*)d_in[4];
    const float* ln2_b    = (const float*)d_in[5];
    const float* ln3_g    = (const float*)d_in[6];
    const float* ln3_b    = (const float*)d_in[7];
    const float* ln4_g    = (const float*)d_in[8];
    const float* ln4_b    = (const float*)d_in[9];
    const float* fc_in_w  = (const float*)d_in[10];
    const float* fc_in_b  = (const float*)d_in[11];
    const float* fc_out_w = (const float*)d_in[12];
    const float* fc_out_b = (const float*)d_in[13];
    const float* a1_q     = (const float*)d_in[14];
    const float* a1_k     = (const float*)d_in[15];
    const float* a1_v     = (const float*)d_in[16];
    const float* a1_o     = (const float*)d_in[17];
    const float* a1_ob    = (const float*)d_in[18];
    const float* a2_q     = (const float*)d_in[19];
    const float* a2_k     = (const float*)d_in[20];
    const float* a2_v     = (const float*)d_in[21];
    const float* a2_o     = (const float*)d_in[22];
    const float* a2_ob    = (const float*)d_in[23];
    const float* ff_proj_w = (const float*)d_in[24];
    const float* ff_proj_b = (const float*)d_in[25];
    const float* ff_out_w  = (const float*)d_in[26];
    const float* ff_out_b  = (const float*)d_in[27];

    cudaFuncSetAttribute(gemm_f16_kernel,
                         cudaFuncAttributeMaxDynamicSharedMemorySize, GEMM_SMEM);
    cudaFuncSetAttribute(flash_self_kernel,
                         cudaFuncAttributeMaxDynamicSharedMemorySize, FS_TOTAL_H * 2);
    cudaFuncSetAttribute(flash_cross_kernel,
                         cudaFuncAttributeMaxDynamicSharedMemorySize, CF_TOTAL_H * 2);

    float *x, *bFfp, *gnst;
    __half *th, *qkvh, *qh, *kvh, *kv2h, *glh, *xh;
    __half *whFcIn, *whQkv, *whA1o, *whA2q, *whA2o, *whKv2, *whFfp, *whFfo, *whFco;
    cudaGetSymbolAddress((void**)&x,    g_x);
    cudaGetSymbolAddress((void**)&bFfp, g_bFfp);
    cudaGetSymbolAddress((void**)&gnst, g_gnstats);
    cudaGetSymbolAddress((void**)&th,   g_th);
    cudaGetSymbolAddress((void**)&qkvh, g_qkvh);
    cudaGetSymbolAddress((void**)&qh,   g_qh);
    cudaGetSymbolAddress((void**)&kvh,  g_kvh);
    cudaGetSymbolAddress((void**)&kv2h, g_kv2h);
    cudaGetSymbolAddress((void**)&glh,  g_glh);
    cudaGetSymbolAddress((void**)&xh,   g_xh);
    cudaGetSymbolAddress((void**)&whFcIn, g_whFcIn);
    cudaGetSymbolAddress((void**)&whQkv,  g_whQkv);
    cudaGetSymbolAddress((void**)&whA1o,  g_whA1o);
    cudaGetSymbolAddress((void**)&whA2q,  g_whA2q);
    cudaGetSymbolAddress((void**)&whA2o,  g_whA2o);
    cudaGetSymbolAddress((void**)&whKv2,  g_whKv2);
    cudaGetSymbolAddress((void**)&whFfp,  g_whFfp);
    cudaGetSymbolAddress((void**)&whFfo,  g_whFfo);
    cudaGetSymbolAddress((void**)&whFco,  g_whFco);

    float* out = (float*)d_out;

    // ---- batched weight transpose+convert (ONE launch) ----
    {
        TrJobs jb;
        const float* srcs[NJOBS] = {fc_in_w, a1_q, a1_k, a1_v, a1_o, a2_q,
                                    a2_o, a2_k, a2_v, ff_proj_w, ff_out_w, fc_out_w};
        __half* dsts[NJOBS] = {whFcIn, whQkv, whQkv + (size_t)512 * 512,
                               whQkv + (size_t)1024 * 512, whA1o, whA2q, whA2o,
                               whKv2, whKv2 + (size_t)512 * 1024,
                               whFfp, whFfo, whFco};
        int Rs[NJOBS] = {512, 512, 512, 512, 512, 512, 512, 1024, 1024, 512, 2048, 512};
        int Cs[NJOBS] = {512, 512, 512, 512, 512, 512, 512, 512, 512, 4096, 512, 512};
        int Il[NJOBS] = {0, 0, 0, 0, 0, 0, 0, 0, 0, 1, 0, 0};
        int acc = 0;
        for (int i = 0; i < NJOBS; i++) {
            jb.src[i] = srcs[i]; jb.dst[i] = dsts[i];
            jb.R[i] = Rs[i]; jb.C[i] = Cs[i]; jb.ileave[i] = Il[i];
            jb.tstart[i] = acc;
            acc += (Rs[i] / 32) * (Cs[i] / 32);
        }
        jb.tstart[NJOBS] = acc;
        trcvt_all_kernel<<<acc, dim3(32, 8)>>>(jb);
    }
    cvt_kernel<<<(BATCH * KVLEN * 1024 + 255) / 256, 256>>>(
        in_kv, kvh, BATCH * KVLEN * 1024);
    bias_ileave_kernel<<<8, 256>>>(ff_proj_b, bFfp);

    // 1. GroupNorm: stats then tiled normalize+transpose -> th (half)
    gn_stats_kernel<<<BATCH * 32, 256>>>(in_q, gnst);
    {
        dim3 grid(SPATIAL / 32, DIMC / 32, BATCH);
        gn_write_kernel<<<grid, dim3(32, 8)>>>(in_q, gnst, gn_g, gn_b, th);
    }

    // 2. x = th @ fc_in + b (fp32)
    gemm(th, 512, whFcIn, 512, x, nullptr, 512, nullptr, 0, fc_in_b,
         NTOK, 512, 512);

    // ---- self attention ----
    layernorm_kernel<<<NTOK / 8, 256>>>(x, ln2_g, ln2_b, th, NTOK);
    gemm(th, 512, whQkv, 512, nullptr, qkvh, 1536, nullptr, 0, nullptr,
         NTOK, 1536, 512);
    {
        dim3 grid(8, 64);
        flash_self_kernel<<<grid, 256, FS_TOTAL_H * 2>>>(qkvh, th);
    }
    gemm(th, 512, whA1o, 512, x, nullptr, 512, x, 512, a1_ob,
         NTOK, 512, 512);

    // ---- cross attention ----
    layernorm_kernel<<<NTOK / 8, 256>>>(x, ln3_g, ln3_b, th, NTOK);
    gemm(th, 512, whA2q, 512, nullptr, qh, 512, nullptr, 0, nullptr,
         NTOK, 512, 512);
    gemm(kvh, 1024, whKv2, 1024, nullptr, kv2h, 1024, nullptr, 0, nullptr,
         BATCH * KVLEN, 1024, 1024);
    {
        dim3 grid(8, 64);
        flash_cross_kernel<<<grid, 256, CF_TOTAL_H * 2>>>(qh, kv2h, th);
    }
    gemm(th, 512, whA2o, 512, x, nullptr, 512, x, 512, a2_ob,
         NTOK, 512, 512);

    // ---- feed-forward (GEGLU, single interleaved GEMM) ----
    layernorm_kernel<<<NTOK / 8, 256>>>(x, ln4_g, ln4_b, th, NTOK);
    gemm(th, 512, whFfp, 512, nullptr, glh, 2048, nullptr, 0, bFfp,
         NTOK, 4096, 512, 3);
    gemm(glh, 2048, whFfo, 2048, nullptr, xh, 512, x, 512, ff_out_b,
         NTOK, 512, 2048);

    // ---- output projection, transposed: out[b,c,s] = fco + qin ----
    gemm(whFco, 512, xh, 512, out, nullptr, 0, in_q, 0, fc_out_b,
         512, NTOK, 512, 4);
}